// round 16
// baseline (speedup 1.0000x reference)
#include <cuda_runtime.h>
#include <cuda_bf16.h>
#include <cuda_fp16.h>
#include <cstdint>
#include <math.h>

// ============================================================
// R16: QK switched to int8 hi/lo (m16n8k32 IMMA, s32 acc):
//   S*sq*sk = Qh*Kh + (Qh*Kl + Ql*Kh)/256, low terms share an
//   accumulator. Per-row scales; dequant via magic-number trick,
//   folded into the existing per-element scale multiply.
// PV unchanged (single fp16 term). Persistent tickets, 2 CTAs/SM,
// 2-stage cp.async ring, log2 softmax, per-lane l (R15 frame).
// ============================================================

constexpr int kS = 2048, kD = 128, kBQ = 64, kBK = 64;
constexpr int kThreads = 128;
constexpr int kIters = kS / kBK;            // 32
constexpr int kQTiles = kS / kBQ;           // 32
constexpr int kTiles  = kQTiles * 32;       // 1024
constexpr int kPersistentCTAs = 304;

// gmem blob layout per (bh,kt): khi8[64x128] | klo8[64x128] | vfp16 image | ksc[64]
constexpr int BKHI = 0;            // 8192
constexpr int BKLO = 8192;         // 8192
constexpr int BVH  = 16384;        // 64 rows x 272B = 17408
constexpr int BKSC = 33792;        // 64 floats = 256
constexpr int kBlobB = 34048;

// smem stage layout: khi[64x144] | klo[64x144] | v image | ksc
constexpr int SKHI = 0;            // 9216
constexpr int SKLO = 9216;         // 9216
constexpr int SVH  = 18432;        // 17408
constexpr int SKSC = 35840;        // 256
constexpr int kStageB = 36096;
constexpr int kSmemBytes = 2 * kStageB + 16;   // 72208

constexpr int kVStrideB = 272;     // V image row stride (unchanged)

__device__ __align__(16) unsigned char g_kv[32u * 32u * (unsigned)kBlobB];
__device__ int g_ticket;

__device__ __forceinline__ uint32_t smem_u32(const void* p) {
    uint32_t a;
    asm("{ .reg .u64 t; cvta.to.shared.u64 t, %1; cvt.u32.u64 %0, t; }" : "=r"(a) : "l"(p));
    return a;
}
__device__ __forceinline__ void cp16(uint32_t dst, const void* src) {
    asm volatile("cp.async.cg.shared.global [%0], [%1], 16;" :: "r"(dst), "l"(src));
}
__device__ __forceinline__ void cp_commit() { asm volatile("cp.async.commit_group;" ::: "memory"); }
__device__ __forceinline__ void cp_wait0()  { asm volatile("cp.async.wait_group 0;" ::: "memory"); }

__device__ __forceinline__ uint32_t lds32(uint32_t addr) {
    uint32_t v;
    asm volatile("ld.shared.b32 %0, [%1];" : "=r"(v) : "r"(addr));
    return v;
}
__device__ __forceinline__ void ldsm_x4_t(uint32_t& r0, uint32_t& r1, uint32_t& r2, uint32_t& r3,
                                          uint32_t addr) {
    asm volatile("ldmatrix.sync.aligned.m8n8.x4.trans.shared.b16 {%0,%1,%2,%3}, [%4];"
        : "=r"(r0), "=r"(r1), "=r"(r2), "=r"(r3) : "r"(addr));
}
__device__ __forceinline__ void mma_s8(int* d, const uint32_t* a, uint32_t b0, uint32_t b1) {
    asm volatile("mma.sync.aligned.m16n8k32.row.col.s32.s8.s8.s32 "
        "{%0,%1,%2,%3}, {%4,%5,%6,%7}, {%8,%9}, {%0,%1,%2,%3};"
        : "+r"(d[0]), "+r"(d[1]), "+r"(d[2]), "+r"(d[3])
        : "r"(a[0]), "r"(a[1]), "r"(a[2]), "r"(a[3]), "r"(b0), "r"(b1));
}
__device__ __forceinline__ void mma_f16(float* d, const uint32_t* a, uint32_t b0, uint32_t b1) {
    asm volatile("mma.sync.aligned.m16n8k16.row.col.f32.f16.f16.f32 "
        "{%0,%1,%2,%3}, {%4,%5,%6,%7}, {%8,%9}, {%0,%1,%2,%3};"
        : "+f"(d[0]), "+f"(d[1]), "+f"(d[2]), "+f"(d[3])
        : "r"(a[0]), "r"(a[1]), "r"(a[2]), "r"(a[3]), "r"(b0), "r"(b1));
}
__device__ __forceinline__ float ex2(float x) {
    float r;
    asm("ex2.approx.ftz.f32 %0, %1;" : "=f"(r) : "f"(x));
    return r;
}
__device__ __forceinline__ uint32_t packh(float a, float b) {
    __half2 t = __floats2half2_rn(a, b);
    return *reinterpret_cast<uint32_t*>(&t);
}
__device__ __forceinline__ int q8clamp(float v) {
    int i = __float2int_rn(v);
    return max(-127, min(127, i));
}
__device__ __forceinline__ uint32_t pack4(int a, int b, int c, int d) {
    return (uint32_t)(a & 255) | ((uint32_t)(b & 255) << 8) |
           ((uint32_t)(c & 255) << 16) | ((uint32_t)(d & 255) << 24);
}
// quantize 4 floats: hi = rn(v*s) in [-127,127]; lo = rn((v*s - hi)*256)
__device__ __forceinline__ void quant4(float4 f, float s, uint32_t& hi, uint32_t& lo) {
    const float x0 = f.x * s, x1 = f.y * s, x2 = f.z * s, x3 = f.w * s;
    const int h0 = q8clamp(x0), h1 = q8clamp(x1), h2 = q8clamp(x2), h3 = q8clamp(x3);
    const int l0 = q8clamp((x0 - (float)h0) * 256.f);
    const int l1 = q8clamp((x1 - (float)h1) * 256.f);
    const int l2 = q8clamp((x2 - (float)h2) * 256.f);
    const int l3 = q8clamp((x3 - (float)h3) * 256.f);
    hi = pack4(h0, h1, h2, h3);
    lo = pack4(l0, l1, l2, l3);
}
// magic-number s32 -> float (exact for |v| < 2^22)
__device__ __forceinline__ float imagic(int v) {
    return __int_as_float(0x4B400000 + v);
}
__device__ __forceinline__ float decode_scalar(const void* p) {
    const int w = *reinterpret_cast<const int*>(p);
    if (w > -(1 << 23) && w < (1 << 23)) return (float)w;
    return __int_as_float(w);
}

// ---------------- precompute: K -> int8 hi/lo + row scales, V -> fp16 image ----------------
__global__ __launch_bounds__(256, 4)
void convert_kv_kernel(const float* __restrict__ k, const float* __restrict__ v) {
    const int kt = (int)blockIdx.x, bh = (int)blockIdx.y, tid = (int)threadIdx.x;
    if (kt == 0 && bh == 0 && tid == 0) g_ticket = 0;
    unsigned char* blob = g_kv + (size_t)(bh * 32 + kt) * kBlobB;
    const float* kgt = k + ((size_t)bh * kS + (size_t)kt * kBK) * kD;
    const float* vgt = v + ((size_t)bh * kS + (size_t)kt * kBK) * kD;

    // ---- K: 4 threads per row (64 rows), each handles 32 cols ----
    {
        const int row = tid >> 2, qt4 = tid & 3;
        const float* krow = kgt + (size_t)row * kD + qt4 * 32;
        float4 f[8];
        float am = 0.f;
        #pragma unroll
        for (int j = 0; j < 8; ++j) {
            f[j] = reinterpret_cast<const float4*>(krow)[j];
            am = fmaxf(am, fmaxf(fmaxf(fabsf(f[j].x), fabsf(f[j].y)),
                                 fmaxf(fabsf(f[j].z), fabsf(f[j].w))));
        }
        am = fmaxf(am, __shfl_xor_sync(0xffffffffu, am, 1));
        am = fmaxf(am, __shfl_xor_sync(0xffffffffu, am, 2));
        am = fmaxf(am, 1e-20f);
        const float s = 127.f / am;
        uint32_t hi[8], lo[8];
        #pragma unroll
        for (int j = 0; j < 8; ++j) quant4(f[j], s, hi[j], lo[j]);
        uint4* dh = reinterpret_cast<uint4*>(blob + BKHI + row * 128 + qt4 * 32);
        uint4* dl = reinterpret_cast<uint4*>(blob + BKLO + row * 128 + qt4 * 32);
        dh[0] = make_uint4(hi[0], hi[1], hi[2], hi[3]);
        dh[1] = make_uint4(hi[4], hi[5], hi[6], hi[7]);
        dl[0] = make_uint4(lo[0], lo[1], lo[2], lo[3]);
        dl[1] = make_uint4(lo[4], lo[5], lo[6], lo[7]);
        if (qt4 == 0) reinterpret_cast<float*>(blob + BKSC)[row] = am / 127.f;  // 1/s_k
    }

    // ---- V: fp16 padded image (unchanged layout) ----
    #pragma unroll
    for (int it = 0; it < 8; ++it) {
        const int idx = it * 256 + tid;            // 2048 float4
        const int r = idx >> 5, c = (idx & 31) << 2;
        const float4 x = reinterpret_cast<const float4*>(vgt)[idx];
        *reinterpret_cast<uint2*>(blob + BVH + r * kVStrideB + c * 2) =
            make_uint2(packh(x.x, x.y), packh(x.z, x.w));
    }
}

// ---------------- main persistent kernel ----------------
__global__ __launch_bounds__(kThreads, 2)
void flash_mma_kernel(const float* __restrict__ q,
                      const float* __restrict__ sf,
                      const void*  __restrict__ dropout_p,
                      float* __restrict__ out) {
    extern __shared__ char smem[];
    const uint32_t sb = smem_u32(smem);
    int* ticket_sm  = reinterpret_cast<int*>(smem + 2 * kStageB);
    int* ticket_sm2 = ticket_sm + 1;
    const int tid  = (int)threadIdx.x;
    const int wid  = tid >> 5;
    const int lane = tid & 31;
    const int g    = lane >> 2;
    const int t    = lane & 3;
    const int w8   = lane & 7;
    const int b3   = (lane >> 3) & 1;
    const int b4   = (lane >> 4) & 1;
    constexpr float kLog2e = 1.4426950408889634f;
    constexpr float kH = 0.00390625f;              // 1/256
    constexpr float kC1 = 12582912.f + 49152.f;    // magic*(1+1/256)
    const float dp = decode_scalar(dropout_p);

    auto copy_blob = [&](int bh, int kt, int stage) {
        const unsigned char* src = g_kv + (size_t)(bh * 32 + kt) * kBlobB;
        const uint32_t dst = sb + (uint32_t)stage * kStageB;
        #pragma unroll
        for (int i = 0; i < 17; ++i) {
            const int op = i * kThreads + tid;     // 2128 ops
            if (op < 1024) {
                const int half = op >> 9;          // 0=khi, 1=klo
                const int r = (op >> 3) & 63, s = op & 7;
                cp16(dst + (uint32_t)(half * 9216 + r * 144 + s * 16),
                     src + half * 8192 + r * 128 + s * 16);
            } else if (op < 2112) {
                const int j = op - 1024;
                cp16(dst + (uint32_t)(SVH + j * 16), src + BVH + j * 16);
            } else if (op < 2128) {
                const int j = op - 2112;
                cp16(dst + (uint32_t)(SKSC + j * 16), src + BKSC + j * 16);
            }
        }
        cp_commit();
    };

    if (tid == 0) *ticket_sm = atomicAdd(&g_ticket, 1);
    __syncthreads();
    int tile = *ticket_sm;
    if (tile < kTiles) copy_blob(tile >> 5, 0, 0);

    while (tile < kTiles) {
        const int qt = tile & (kQTiles - 1);
        const int bh = tile >> 5;

        // ---- Q: load, per-row absmax, int8 hi/lo quantize (A-frags) ----
        const float* qg = q + ((size_t)bh * kS + (size_t)qt * kBQ) * kD;
        const float* rq0 = qg + (size_t)(wid * 16 + g) * kD;
        const float* rq8 = rq0 + 8 * kD;
        float4 q0a[4], q0b[4], q1a[4], q1b[4];
        float am0 = 0.f, am1 = 0.f;
        #pragma unroll
        for (int ks = 0; ks < 4; ++ks) {
            const int c = ks * 32 + 4 * t;
            q0a[ks] = *reinterpret_cast<const float4*>(rq0 + c);
            q0b[ks] = *reinterpret_cast<const float4*>(rq0 + c + 16);
            q1a[ks] = *reinterpret_cast<const float4*>(rq8 + c);
            q1b[ks] = *reinterpret_cast<const float4*>(rq8 + c + 16);
            am0 = fmaxf(am0, fmaxf(fmaxf(fabsf(q0a[ks].x), fabsf(q0a[ks].y)),
                                   fmaxf(fabsf(q0a[ks].z), fabsf(q0a[ks].w))));
            am0 = fmaxf(am0, fmaxf(fmaxf(fabsf(q0b[ks].x), fabsf(q0b[ks].y)),
                                   fmaxf(fabsf(q0b[ks].z), fabsf(q0b[ks].w))));
            am1 = fmaxf(am1, fmaxf(fmaxf(fabsf(q1a[ks].x), fabsf(q1a[ks].y)),
                                   fmaxf(fabsf(q1a[ks].z), fabsf(q1a[ks].w))));
            am1 = fmaxf(am1, fmaxf(fmaxf(fabsf(q1b[ks].x), fabsf(q1b[ks].y)),
                                   fmaxf(fabsf(q1b[ks].z), fabsf(q1b[ks].w))));
        }
        #pragma unroll
        for (int off = 1; off <= 2; off <<= 1) {
            am0 = fmaxf(am0, __shfl_xor_sync(0xffffffffu, am0, off));
            am1 = fmaxf(am1, __shfl_xor_sync(0xffffffffu, am1, off));
        }
        am0 = fmaxf(am0, 1e-20f);
        am1 = fmaxf(am1, 1e-20f);
        const float sq0 = 127.f / am0, isq0 = am0 / 127.f;
        const float sq1 = 127.f / am1, isq1 = am1 / 127.f;
        uint32_t qh[4][4], ql[4][4];
        #pragma unroll
        for (int ks = 0; ks < 4; ++ks) {
            quant4(q0a[ks], sq0, qh[ks][0], ql[ks][0]);
            quant4(q1a[ks], sq1, qh[ks][1], ql[ks][1]);
            quant4(q0b[ks], sq0, qh[ks][2], ql[ks][2]);
            quant4(q1b[ks], sq1, qh[ks][3], ql[ks][3]);
        }

        float oacc[16][4];
        #pragma unroll
        for (int n = 0; n < 16; ++n)
            #pragma unroll
            for (int c = 0; c < 4; ++c) oacc[n][c] = 0.f;
        float m0 = -INFINITY, m1 = -INFINITY, l0 = 0.f, l1 = 0.f;

        const float* scr0 = sf + ((size_t)(qt * kBQ) + (size_t)(wid * 16 + g)) * kS + 2 * t;
        const float* scr1 = scr0 + (size_t)8 * kS;

        for (int kt = 0; kt < kIters; ++kt) {
            cp_wait0();
            __syncthreads();
            if (kt + 1 < kIters) copy_blob(bh, kt + 1, (kt + 1) & 1);
            if (kt == kIters - 1 && tid == 0) *ticket_sm2 = atomicAdd(&g_ticket, 1);

            const int st = kt & 1;
            const uint32_t stOff = (uint32_t)st * kStageB;
            const uint32_t KHIs = sb + stOff + SKHI;
            const uint32_t VHs  = sb + stOff + SVH;

            const float* scg0 = scr0 + (size_t)kt * kBK;
            const float* scg1 = scr1 + (size_t)kt * kBK;
            float2 sc0[8], sc1[8];
            #pragma unroll
            for (int n = 0; n < 8; ++n) {
                sc0[n] = *reinterpret_cast<const float2*>(scg0 + n * 8);
                sc1[n] = *reinterpret_cast<const float2*>(scg1 + n * 8);
                sc0[n].x *= kLog2e; sc0[n].y *= kLog2e;
                sc1[n].x *= kLog2e; sc1[n].y *= kLog2e;
            }

            // ---- S*sq*sk = Qh Kh + (Qh Kl + Ql Kh)/256  (int8 IMMA) ----
            int hh[8][4], lw[8][4];
            #pragma unroll
            for (int n = 0; n < 8; ++n)
                #pragma unroll
                for (int c = 0; c < 4; ++c) { hh[n][c] = 0; lw[n][c] = 0; }

            #pragma unroll
            for (int ks = 0; ks < 4; ++ks) {
                #pragma unroll
                for (int n = 0; n < 8; ++n) {
                    const uint32_t base = KHIs + (uint32_t)((n * 8 + g) * 144 + ks * 32 + 4 * t);
                    const uint32_t bh0 = lds32(base);
                    const uint32_t bh1 = lds32(base + 16);
                    const uint32_t bl0 = lds32(base + 9216);
                    const uint32_t bl1 = lds32(base + 9216 + 16);
                    mma_s8(hh[n], qh[ks], bh0, bh1);
                    mma_s8(lw[n], qh[ks], bl0, bl1);
                    mma_s8(lw[n], ql[ks], bh0, bh1);
                }
            }

            // ---- dequant + per-element scale (log2 domain) ----
            float sacc[8][4];
            #pragma unroll
            for (int n = 0; n < 8; ++n) {
                const float2 kk = *reinterpret_cast<const float2*>(
                    smem + stOff + SKSC + n * 32 + t * 8);
                const float t0x = kk.x * isq0, t0y = kk.y * isq0;
                const float t1x = kk.x * isq1, t1y = kk.y * isq1;
                const float f0 = fmaf(imagic(lw[n][0]), kH, imagic(hh[n][0])) - kC1;
                const float f1 = fmaf(imagic(lw[n][1]), kH, imagic(hh[n][1])) - kC1;
                const float f2 = fmaf(imagic(lw[n][2]), kH, imagic(hh[n][2])) - kC1;
                const float f3 = fmaf(imagic(lw[n][3]), kH, imagic(hh[n][3])) - kC1;
                sacc[n][0] = f0 * t0x * sc0[n].x;
                sacc[n][1] = f1 * t0y * sc0[n].y;
                sacc[n][2] = f2 * t1x * sc1[n].x;
                sacc[n][3] = f3 * t1y * sc1[n].y;
            }

            // ---- online softmax ----
            float mx0 = -INFINITY, mx1 = -INFINITY;
            #pragma unroll
            for (int n = 0; n < 8; ++n) {
                mx0 = fmaxf(mx0, fmaxf(sacc[n][0], sacc[n][1]));
                mx1 = fmaxf(mx1, fmaxf(sacc[n][2], sacc[n][3]));
            }
            #pragma unroll
            for (int off = 1; off <= 2; off <<= 1) {
                mx0 = fmaxf(mx0, __shfl_xor_sync(0xffffffffu, mx0, off));
                mx1 = fmaxf(mx1, __shfl_xor_sync(0xffffffffu, mx1, off));
            }
            const float m0n = fmaxf(m0, mx0), m1n = fmaxf(m1, mx1);
            const float a0 = ex2(m0 - m0n), a1 = ex2(m1 - m1n);
            m0 = m0n; m1 = m1n;

            float sum0 = 0.f, sum1 = 0.f;
            #pragma unroll
            for (int n = 0; n < 8; ++n) {
                sacc[n][0] = ex2(sacc[n][0] - m0n);
                sacc[n][1] = ex2(sacc[n][1] - m0n);
                sacc[n][2] = ex2(sacc[n][2] - m1n);
                sacc[n][3] = ex2(sacc[n][3] - m1n);
                sum0 += sacc[n][0] + sacc[n][1];
                sum1 += sacc[n][2] + sacc[n][3];
            }
            l0 = l0 * a0 + sum0;
            l1 = l1 * a1 + sum1;

            #pragma unroll
            for (int n = 0; n < 16; ++n) {
                oacc[n][0] *= a0; oacc[n][1] *= a0;
                oacc[n][2] *= a1; oacc[n][3] *= a1;
            }

            // ---- repack P (fp16) -> A-frags ----
            uint32_t phi[4][4];
            #pragma unroll
            for (int j = 0; j < 4; ++j) {
                phi[j][0] = packh(sacc[2*j][0],   sacc[2*j][1]);
                phi[j][1] = packh(sacc[2*j][2],   sacc[2*j][3]);
                phi[j][2] = packh(sacc[2*j+1][0], sacc[2*j+1][1]);
                phi[j][3] = packh(sacc[2*j+1][2], sacc[2*j+1][3]);
            }

            // ---- O += P V (single fp16 term) ----
            #pragma unroll
            for (int j = 0; j < 4; ++j) {
                #pragma unroll
                for (int pp = 0; pp < 8; ++pp) {
                    const uint32_t off = (uint32_t)((j * 16 + b3 * 8 + w8) * kVStrideB
                                                    + (pp * 16 + b4 * 8) * 2);
                    uint32_t vh0, vh1, vh2, vh3;
                    ldsm_x4_t(vh0, vh1, vh2, vh3, VHs + off);
                    mma_f16(oacc[2*pp],   phi[j], vh0, vh1);
                    mma_f16(oacc[2*pp+1], phi[j], vh2, vh3);
                }
            }
        }

        // ---- next ticket + stage-0 prefetch before epilogue ----
        __syncthreads();
        const int next = *ticket_sm2;
        if (next < kTiles) copy_blob(next >> 5, 0, 0);

        // ---- per-tile epilogue ----
        float L0 = l0, L1 = l1;
        #pragma unroll
        for (int off = 1; off <= 2; off <<= 1) {
            L0 += __shfl_xor_sync(0xffffffffu, L0, off);
            L1 += __shfl_xor_sync(0xffffffffu, L1, off);
        }
        const float inv0 = dp / L0, inv1 = dp / L1;
        const size_t row0 = (size_t)bh * kS + (size_t)qt * kBQ + (size_t)(wid * 16 + g);
        float* o0 = out + row0 * kD + 2 * t;
        float* o1 = o0 + (size_t)8 * kD;
        #pragma unroll
        for (int n = 0; n < 16; ++n) {
            *reinterpret_cast<float2*>(o0 + n * 8) = make_float2(oacc[n][0] * inv0, oacc[n][1] * inv0);
            *reinterpret_cast<float2*>(o1 + n * 8) = make_float2(oacc[n][2] * inv1, oacc[n][3] * inv1);
        }

        tile = next;
    }
}

extern "C" void kernel_launch(void* const* d_in, const int* in_sizes, int n_in,
                              void* d_out, int out_size) {
    const float* q  = (const float*)d_in[0];
    const float* k  = (const float*)d_in[1];
    const float* v  = (const float*)d_in[2];
    const float* sf = (const float*)d_in[3];
    const void*  dp = d_in[4];
    float* out = (float*)d_out;
    (void)in_sizes; (void)n_in; (void)out_size;

    dim3 cgrid(kIters, 32);
    convert_kv_kernel<<<cgrid, 256>>>(k, v);   // also resets g_ticket

    cudaFuncSetAttribute(flash_mma_kernel,
                         cudaFuncAttributeMaxDynamicSharedMemorySize, kSmemBytes);
    flash_mma_kernel<<<kPersistentCTAs, kThreads, kSmemBytes>>>(q, sf, dp, out);
}

// round 17
// speedup vs baseline: 2.3235x; 2.3235x over previous
#include <cuda_runtime.h>
#include <cuda_bf16.h>
#include <cuda_fp16.h>
#include <cstdint>
#include <math.h>

// ============================================================
// R17: R15 hot loop (QK bf16 3-term, PV single fp16, log2 softmax,
// per-lane l, persistent tickets, 2 CTAs/SM, 2-stage cp.async ring)
// with SPLIT-K work items: item = (bh, qt, k-half), 2048 items of
// 16 k-iters -> tail imbalance 15% -> ~4%. Main kernel stores
// unnormalized partials (O, m, l); a merge kernel combines the two
// halves exactly (online-softmax combine) and normalizes.
// ============================================================

constexpr int kS = 2048, kD = 128, kBQ = 64, kBK = 64;
constexpr int kThreads = 128;
constexpr int kQTiles = 32;
constexpr int kItems  = 32 * kQTiles * 2;      // 2048 work items
constexpr int kItersH = 16;                    // k-iters per half
constexpr int kPersistentCTAs = 304;

constexpr int kKVStrideB = 272;
constexpr int kKVTileB   = 64 * kKVStrideB;    // 17408
constexpr int kBlobB     = 3 * kKVTileB;       // khi,klo,vhi = 52224
constexpr int kKVOps     = kBlobB / 16;        // 3264
constexpr int kSmemBytes = 2 * kBlobB + 16;    // 104464

// partial per item: O[64][128] | m[64] | l[64]  = 8320 floats
constexpr int kPartF = 8320;

__device__ __align__(16) unsigned char g_kv[32u * 32u * (unsigned)kBlobB];
__device__ __align__(16) float g_part[(size_t)kItems * kPartF];
__device__ int g_ticket;

__device__ __forceinline__ uint32_t smem_u32(const void* p) {
    uint32_t a;
    asm("{ .reg .u64 t; cvta.to.shared.u64 t, %1; cvt.u32.u64 %0, t; }" : "=r"(a) : "l"(p));
    return a;
}
__device__ __forceinline__ void cp16(uint32_t dst, const void* src) {
    asm volatile("cp.async.cg.shared.global [%0], [%1], 16;" :: "r"(dst), "l"(src));
}
__device__ __forceinline__ void cp_commit() { asm volatile("cp.async.commit_group;" ::: "memory"); }
__device__ __forceinline__ void cp_wait0()  { asm volatile("cp.async.wait_group 0;" ::: "memory"); }

__device__ __forceinline__ void ldsm_x4(uint32_t& r0, uint32_t& r1, uint32_t& r2, uint32_t& r3,
                                        uint32_t addr) {
    asm volatile("ldmatrix.sync.aligned.m8n8.x4.shared.b16 {%0,%1,%2,%3}, [%4];"
        : "=r"(r0), "=r"(r1), "=r"(r2), "=r"(r3) : "r"(addr));
}
__device__ __forceinline__ void ldsm_x4_t(uint32_t& r0, uint32_t& r1, uint32_t& r2, uint32_t& r3,
                                          uint32_t addr) {
    asm volatile("ldmatrix.sync.aligned.m8n8.x4.trans.shared.b16 {%0,%1,%2,%3}, [%4];"
        : "=r"(r0), "=r"(r1), "=r"(r2), "=r"(r3) : "r"(addr));
}
__device__ __forceinline__ void mma_bf16(float* d, const uint32_t* a, uint32_t b0, uint32_t b1) {
    asm volatile("mma.sync.aligned.m16n8k16.row.col.f32.bf16.bf16.f32 "
        "{%0,%1,%2,%3}, {%4,%5,%6,%7}, {%8,%9}, {%0,%1,%2,%3};"
        : "+f"(d[0]), "+f"(d[1]), "+f"(d[2]), "+f"(d[3])
        : "r"(a[0]), "r"(a[1]), "r"(a[2]), "r"(a[3]), "r"(b0), "r"(b1));
}
__device__ __forceinline__ void mma_f16(float* d, const uint32_t* a, uint32_t b0, uint32_t b1) {
    asm volatile("mma.sync.aligned.m16n8k16.row.col.f32.f16.f16.f32 "
        "{%0,%1,%2,%3}, {%4,%5,%6,%7}, {%8,%9}, {%0,%1,%2,%3};"
        : "+f"(d[0]), "+f"(d[1]), "+f"(d[2]), "+f"(d[3])
        : "r"(a[0]), "r"(a[1]), "r"(a[2]), "r"(a[3]), "r"(b0), "r"(b1));
}
__device__ __forceinline__ float ex2(float x) {
    float r;
    asm("ex2.approx.ftz.f32 %0, %1;" : "=f"(r) : "f"(x));
    return r;
}
__device__ __forceinline__ uint32_t packbf(float a, float b) {
    __nv_bfloat162 t = __floats2bfloat162_rn(a, b);
    return *reinterpret_cast<uint32_t*>(&t);
}
__device__ __forceinline__ uint32_t packh(float a, float b) {
    __half2 t = __floats2half2_rn(a, b);
    return *reinterpret_cast<uint32_t*>(&t);
}
__device__ __forceinline__ void split2(float a, float b, uint32_t& hi, uint32_t& lo) {
    __nv_bfloat16 ah = __float2bfloat16(a), bh = __float2bfloat16(b);
    __nv_bfloat162 h; h.x = ah; h.y = bh;
    hi = *reinterpret_cast<uint32_t*>(&h);
    lo = packbf(a - __bfloat162float(ah), b - __bfloat162float(bh));
}
__device__ __forceinline__ float decode_scalar(const void* p) {
    const int w = *reinterpret_cast<const int*>(p);
    if (w > -(1 << 23) && w < (1 << 23)) return (float)w;
    return __int_as_float(w);
}

// ---------------- precompute: K -> bf16 hi/lo, V -> fp16; resets ticket ----------------
__global__ __launch_bounds__(256, 4)
void convert_kv_kernel(const float* __restrict__ k, const float* __restrict__ v) {
    const int kt = (int)blockIdx.x, bh = (int)blockIdx.y, tid = (int)threadIdx.x;
    if (kt == 0 && bh == 0 && tid == 0) g_ticket = 0;
    unsigned char* blob = g_kv + (size_t)(bh * 32 + kt) * kBlobB;
    const float* kgt = k + ((size_t)bh * kS + (size_t)kt * kBK) * kD;
    const float* vgt = v + ((size_t)bh * kS + (size_t)kt * kBK) * kD;
    #pragma unroll
    for (int it = 0; it < 8; ++it) {
        const int idx = it * 256 + tid;
        const int r = idx >> 5, c = (idx & 31) << 2;
        const int so = r * kKVStrideB + c * 2;
        {
            const float4 x = reinterpret_cast<const float4*>(kgt)[idx];
            uint32_t h0, l0, h1, l1;
            split2(x.x, x.y, h0, l0);
            split2(x.z, x.w, h1, l1);
            *reinterpret_cast<uint2*>(blob + so)            = make_uint2(h0, h1);
            *reinterpret_cast<uint2*>(blob + kKVTileB + so) = make_uint2(l0, l1);
        }
        {
            const float4 x = reinterpret_cast<const float4*>(vgt)[idx];
            *reinterpret_cast<uint2*>(blob + 2 * kKVTileB + so) =
                make_uint2(packh(x.x, x.y), packh(x.z, x.w));
        }
    }
}

// ---------------- main persistent kernel: computes per-half partials ----------------
__global__ __launch_bounds__(kThreads, 2)
void flash_mma_kernel(const float* __restrict__ q,
                      const float* __restrict__ sf) {
    extern __shared__ char smem[];
    const uint32_t sb = smem_u32(smem);
    int* ticket_sm  = reinterpret_cast<int*>(smem + 2 * kBlobB);
    int* ticket_sm2 = ticket_sm + 1;
    const int tid  = (int)threadIdx.x;
    const int wid  = tid >> 5;
    const int lane = tid & 31;
    const int g    = lane >> 2;
    const int t    = lane & 3;
    const int w8   = lane & 7;
    const int b3   = (lane >> 3) & 1;
    const int b4   = (lane >> 4) & 1;
    constexpr float kLog2e = 1.4426950408889634f;

    auto copy_blob = [&](int bh, int kt, int stage) {
        const unsigned char* src = g_kv + (size_t)(bh * 32 + kt) * kBlobB;
        const uint32_t dkv = sb + (uint32_t)stage * kBlobB;
        #pragma unroll
        for (int i = 0; i < 26; ++i) {
            const int op = i * kThreads + tid;
            if (op < kKVOps) cp16(dkv + op * 16, src + (size_t)op * 16);
        }
        cp_commit();
    };

    if (tid == 0) *ticket_sm = atomicAdd(&g_ticket, 1);
    __syncthreads();
    int item = *ticket_sm;
    if (item < kItems) copy_blob(item >> 6, (item & 1) << 4, 0);

    while (item < kItems) {
        const int bh   = item >> 6;
        const int qt   = (item >> 1) & 31;
        const int kt0  = (item & 1) << 4;

        // ---- Q fragments (bf16 hi/lo) ----
        const float* qg = q + ((size_t)bh * kS + (size_t)qt * kBQ) * kD;
        uint32_t qhi[8][4], qlo[8][4];
        {
            const float* rq0 = qg + (size_t)(wid * 16 + g) * kD;
            const float* rq8 = rq0 + 8 * kD;
            #pragma unroll
            for (int ks = 0; ks < 8; ++ks) {
                const int c = ks * 16 + 2 * t;
                const float2 f0 = *reinterpret_cast<const float2*>(rq0 + c);
                const float2 f1 = *reinterpret_cast<const float2*>(rq8 + c);
                const float2 f2 = *reinterpret_cast<const float2*>(rq0 + c + 8);
                const float2 f3 = *reinterpret_cast<const float2*>(rq8 + c + 8);
                split2(f0.x, f0.y, qhi[ks][0], qlo[ks][0]);
                split2(f1.x, f1.y, qhi[ks][1], qlo[ks][1]);
                split2(f2.x, f2.y, qhi[ks][2], qlo[ks][2]);
                split2(f3.x, f3.y, qhi[ks][3], qlo[ks][3]);
            }
        }

        float oacc[16][4];
        #pragma unroll
        for (int n = 0; n < 16; ++n)
            #pragma unroll
            for (int c = 0; c < 4; ++c) oacc[n][c] = 0.f;
        float m0 = -INFINITY, m1 = -INFINITY, l0 = 0.f, l1 = 0.f;

        const float* scr0 = sf + ((size_t)(qt * kBQ) + (size_t)(wid * 16 + g)) * kS + 2 * t;
        const float* scr1 = scr0 + (size_t)8 * kS;

        for (int j = 0; j < kItersH; ++j) {
            const int kt = kt0 + j;
            cp_wait0();
            __syncthreads();
            if (j + 1 < kItersH) copy_blob(bh, kt + 1, (j + 1) & 1);
            if (j == kItersH - 1 && tid == 0) *ticket_sm2 = atomicAdd(&g_ticket, 1);

            const int st = j & 1;
            const uint32_t KHI = sb + (uint32_t)st * kBlobB;
            const uint32_t KLO = KHI + kKVTileB;
            const uint32_t VHI = KHI + 2 * kKVTileB;

            const float* scg0 = scr0 + (size_t)kt * kBK;
            const float* scg1 = scr1 + (size_t)kt * kBK;
            float2 sc0[8], sc1[8];
            #pragma unroll
            for (int n = 0; n < 8; ++n) {
                sc0[n] = *reinterpret_cast<const float2*>(scg0 + n * 8);
                sc1[n] = *reinterpret_cast<const float2*>(scg1 + n * 8);
                sc0[n].x *= kLog2e; sc0[n].y *= kLog2e;
                sc1[n].x *= kLog2e; sc1[n].y *= kLog2e;
            }

            // ---- S = Q K^T (bf16 3-term) ----
            float sacc[8][4];
            #pragma unroll
            for (int n = 0; n < 8; ++n)
                #pragma unroll
                for (int c = 0; c < 4; ++c) sacc[n][c] = 0.f;

            #pragma unroll
            for (int ks = 0; ks < 8; ++ks) {
                uint32_t bhi[8][2], blo[8][2];
                #pragma unroll
                for (int p = 0; p < 4; ++p) {
                    const uint32_t off = (uint32_t)((p * 16 + b4 * 8 + w8) * kKVStrideB
                                                    + (ks * 16 + b3 * 8) * 2);
                    ldsm_x4(bhi[2*p][0], bhi[2*p][1], bhi[2*p+1][0], bhi[2*p+1][1], KHI + off);
                    ldsm_x4(blo[2*p][0], blo[2*p][1], blo[2*p+1][0], blo[2*p+1][1], KLO + off);
                }
                #pragma unroll
                for (int n = 0; n < 8; ++n) {
                    mma_bf16(sacc[n], qhi[ks], bhi[n][0], bhi[n][1]);
                    mma_bf16(sacc[n], qhi[ks], blo[n][0], blo[n][1]);
                    mma_bf16(sacc[n], qlo[ks], bhi[n][0], bhi[n][1]);
                }
            }

            // ---- scale (log2 domain) + online softmax ----
            float mx0 = -INFINITY, mx1 = -INFINITY;
            #pragma unroll
            for (int n = 0; n < 8; ++n) {
                sacc[n][0] *= sc0[n].x; sacc[n][1] *= sc0[n].y;
                sacc[n][2] *= sc1[n].x; sacc[n][3] *= sc1[n].y;
                mx0 = fmaxf(mx0, fmaxf(sacc[n][0], sacc[n][1]));
                mx1 = fmaxf(mx1, fmaxf(sacc[n][2], sacc[n][3]));
            }
            #pragma unroll
            for (int off = 1; off <= 2; off <<= 1) {
                mx0 = fmaxf(mx0, __shfl_xor_sync(0xffffffffu, mx0, off));
                mx1 = fmaxf(mx1, __shfl_xor_sync(0xffffffffu, mx1, off));
            }
            const float m0n = fmaxf(m0, mx0), m1n = fmaxf(m1, mx1);
            const float a0 = ex2(m0 - m0n), a1 = ex2(m1 - m1n);
            m0 = m0n; m1 = m1n;

            float sum0 = 0.f, sum1 = 0.f;
            #pragma unroll
            for (int n = 0; n < 8; ++n) {
                sacc[n][0] = ex2(sacc[n][0] - m0n);
                sacc[n][1] = ex2(sacc[n][1] - m0n);
                sacc[n][2] = ex2(sacc[n][2] - m1n);
                sacc[n][3] = ex2(sacc[n][3] - m1n);
                sum0 += sacc[n][0] + sacc[n][1];
                sum1 += sacc[n][2] + sacc[n][3];
            }
            l0 = l0 * a0 + sum0;
            l1 = l1 * a1 + sum1;

            #pragma unroll
            for (int n = 0; n < 16; ++n) {
                oacc[n][0] *= a0; oacc[n][1] *= a0;
                oacc[n][2] *= a1; oacc[n][3] *= a1;
            }

            uint32_t phi[4][4];
            #pragma unroll
            for (int jj = 0; jj < 4; ++jj) {
                phi[jj][0] = packh(sacc[2*jj][0],   sacc[2*jj][1]);
                phi[jj][1] = packh(sacc[2*jj][2],   sacc[2*jj][3]);
                phi[jj][2] = packh(sacc[2*jj+1][0], sacc[2*jj+1][1]);
                phi[jj][3] = packh(sacc[2*jj+1][2], sacc[2*jj+1][3]);
            }

            #pragma unroll
            for (int jj = 0; jj < 4; ++jj) {
                #pragma unroll
                for (int pp = 0; pp < 8; ++pp) {
                    const uint32_t off = (uint32_t)((jj * 16 + b3 * 8 + w8) * kKVStrideB
                                                    + (pp * 16 + b4 * 8) * 2);
                    uint32_t vh0, vh1, vh2, vh3;
                    ldsm_x4_t(vh0, vh1, vh2, vh3, VHI + off);
                    mma_f16(oacc[2*pp],   phi[jj], vh0, vh1);
                    mma_f16(oacc[2*pp+1], phi[jj], vh2, vh3);
                }
            }
        }

        // ---- next ticket; prefetch its stage-0 blob before the partial store ----
        __syncthreads();
        const int next = *ticket_sm2;
        if (next < kItems) copy_blob(next >> 6, (next & 1) << 4, 0);

        // ---- store unnormalized partial (O, m, l) ----
        float L0 = l0, L1 = l1;
        #pragma unroll
        for (int off = 1; off <= 2; off <<= 1) {
            L0 += __shfl_xor_sync(0xffffffffu, L0, off);
            L1 += __shfl_xor_sync(0xffffffffu, L1, off);
        }
        float* part = g_part + (size_t)item * kPartF;
        const int r0 = wid * 16 + g;
        float* p0 = part + (size_t)r0 * kD + 2 * t;
        float* p1 = p0 + (size_t)8 * kD;
        #pragma unroll
        for (int n = 0; n < 16; ++n) {
            *reinterpret_cast<float2*>(p0 + n * 8) = make_float2(oacc[n][0], oacc[n][1]);
            *reinterpret_cast<float2*>(p1 + n * 8) = make_float2(oacc[n][2], oacc[n][3]);
        }
        if (t == 0) {
            part[8192 + r0]     = m0;
            part[8192 + r0 + 8] = m1;
            part[8256 + r0]     = L0;
            part[8256 + r0 + 8] = L1;
        }

        item = next;
    }
}

// ---------------- merge: combine the two k-halves, normalize, write out ----------------
__global__ __launch_bounds__(256)
void merge_kernel(const void* __restrict__ dropout_p, float* __restrict__ out) {
    const int tile = (int)blockIdx.x;          // 0..1023 = bh*32 + qt
    const int bh = tile >> 5, qt = tile & 31;
    const int tid = (int)threadIdx.x;
    const int r = tid >> 2;                    // 0..63
    const int c0 = (tid & 3) * 32;
    const float dp = decode_scalar(dropout_p);

    const float* pa = g_part + (size_t)(tile * 2)     * kPartF;
    const float* pb = g_part + (size_t)(tile * 2 + 1) * kPartF;
    const float ma = pa[8192 + r], mb = pb[8192 + r];
    const float la = pa[8256 + r], lb = pb[8256 + r];
    const float ms = fmaxf(ma, mb);
    const float wa = ex2(ma - ms), wb = ex2(mb - ms);
    const float inv = dp / (la * wa + lb * wb);
    const float fa = wa * inv, fb = wb * inv;

    const float* oa = pa + (size_t)r * kD + c0;
    const float* ob = pb + (size_t)r * kD + c0;
    float* og = out + ((size_t)bh * kS + (size_t)qt * kBQ + r) * kD + c0;
    #pragma unroll
    for (int i = 0; i < 8; ++i) {
        const float4 xa = reinterpret_cast<const float4*>(oa)[i];
        const float4 xb = reinterpret_cast<const float4*>(ob)[i];
        float4 o;
        o.x = xa.x * fa + xb.x * fb;
        o.y = xa.y * fa + xb.y * fb;
        o.z = xa.z * fa + xb.z * fb;
        o.w = xa.w * fa + xb.w * fb;
        reinterpret_cast<float4*>(og)[i] = o;
    }
}

extern "C" void kernel_launch(void* const* d_in, const int* in_sizes, int n_in,
                              void* d_out, int out_size) {
    const float* q  = (const float*)d_in[0];
    const float* k  = (const float*)d_in[1];
    const float* v  = (const float*)d_in[2];
    const float* sf = (const float*)d_in[3];
    const void*  dp = d_in[4];
    float* out = (float*)d_out;
    (void)in_sizes; (void)n_in; (void)out_size;

    dim3 cgrid(32, 32);
    convert_kv_kernel<<<cgrid, 256>>>(k, v);   // also resets g_ticket

    cudaFuncSetAttribute(flash_mma_kernel,
                         cudaFuncAttributeMaxDynamicSharedMemorySize, kSmemBytes);
    flash_mma_kernel<<<kPersistentCTAs, kThreads, kSmemBytes>>>(q, sf);

    merge_kernel<<<32 * kQTiles, 256>>>(dp, out);
}